// round 8
// baseline (speedup 1.0000x reference)
#include <cuda_runtime.h>
#include <math.h>
#include <stdint.h>

#define BB 8
#define NN 1024
#define DIM 192
#define HEADS 16
#define DHEAD 64
#define INNER 1024
#define TOK (BB*NN)       // 8192
#define QKVN (3*INNER)    // 3072

// Scratch (allocation-free rule: __device__ globals)
__device__ float g_h[TOK*DIM];
__device__ float g_qkv[(size_t)TOK*QKVN];
__device__ float g_attn[(size_t)TOK*INNER];
__device__ float g_wqkv[DIM*QKVN];
__device__ float g_wout[INNER*DIM];
__device__ float g_vt[(size_t)BB*HEADS*DHEAD*NN];   // V transposed per (b,h): [d][n]

__device__ __forceinline__ uint32_t f2tf(float x){
    uint32_t u; asm("cvt.rna.tf32.f32 %0, %1;" : "=r"(u) : "f"(x)); return u;
}

// D += A@B, m16n8k8 tf32. c0=[g][2t], c1=[g][2t+1], c2=[g+8][2t], c3=[g+8][2t+1]
__device__ __forceinline__ void mma_tf32(float* c, uint32_t a0, uint32_t a1, uint32_t a2, uint32_t a3,
                                         uint32_t b0, uint32_t b1){
    asm volatile("mma.sync.aligned.m16n8k8.row.col.f32.tf32.tf32.f32 "
        "{%0,%1,%2,%3}, {%4,%5,%6,%7}, {%8,%9}, {%0,%1,%2,%3};"
        : "+f"(c[0]), "+f"(c[1]), "+f"(c[2]), "+f"(c[3])
        : "r"(a0), "r"(a1), "r"(a2), "r"(a3), "r"(b0), "r"(b1));
}

__device__ __forceinline__ void ldsm4(uint32_t* r, uint32_t saddr){
    asm volatile("ldmatrix.sync.aligned.m8n8.x4.shared.b16 {%0,%1,%2,%3}, [%4];"
        : "=r"(r[0]), "=r"(r[1]), "=r"(r[2]), "=r"(r[3]) : "r"(saddr));
}

__device__ __forceinline__ void cpa16(uint32_t dst, const void* src){
    asm volatile("cp.async.cg.shared.global [%0], [%1], 16;" :: "r"(dst), "l"(src));
}
__device__ __forceinline__ void cp_commit(){ asm volatile("cp.async.commit_group;"); }
template<int N> __device__ __forceinline__ void cp_wait(){
    asm volatile("cp.async.wait_group %0;" :: "n"(N));
}

// ---------------------------------------------------------------------------
// Elementwise fp32 -> tf32-rounded fp32 bits (for weights)
// ---------------------------------------------------------------------------
__global__ __launch_bounds__(256)
void cvt_tf32_kernel(const float* __restrict__ src, float* __restrict__ dst, int n){
    for (int i = blockIdx.x*256 + threadIdx.x; i < n; i += gridDim.x*256)
        dst[i] = __uint_as_float(f2tf(src[i]));
}

// ---------------------------------------------------------------------------
// LayerNorm + adaLN modulation: one warp per token; output tf32-rounded
// ---------------------------------------------------------------------------
__global__ __launch_bounds__(256)
void ln_mod_kernel(const float* __restrict__ x,
                   const float* __restrict__ shift,
                   const float* __restrict__ scale,
                   const float* __restrict__ w,
                   const float* __restrict__ bpar) {
    int warp = threadIdx.x >> 5;
    int lane = threadIdx.x & 31;
    int t = blockIdx.x * 8 + warp;
    const float* xr = x + (size_t)t * DIM;
    float v[6];
    float s = 0.f;
#pragma unroll
    for (int q = 0; q < 6; q++) { v[q] = xr[lane + q*32]; s += v[q]; }
#pragma unroll
    for (int o = 16; o; o >>= 1) s += __shfl_xor_sync(0xffffffffu, s, o);
    float mu = s * (1.f/DIM);
    float vs = 0.f;
#pragma unroll
    for (int q = 0; q < 6; q++) { float d = v[q]-mu; vs += d*d; }
#pragma unroll
    for (int o = 16; o; o >>= 1) vs += __shfl_xor_sync(0xffffffffu, vs, o);
    float rstd = rsqrtf(vs*(1.f/DIM) + 1e-5f);
    int bi = t >> 10;
#pragma unroll
    for (int q = 0; q < 6; q++) {
        int d = lane + q*32;
        float hn = (v[q]-mu)*rstd*w[d] + bpar[d];
        hn = hn * (1.f + scale[bi*DIM + d]) + shift[bi*DIM + d];
        g_h[(size_t)t*DIM + d] = __uint_as_float(f2tf(hn));
    }
}

// ---------------------------------------------------------------------------
// V transpose: per (b,h), V[n][d] (1024x64) -> Vt[d][n] (64x1024).
// One CTA per 64-token tile. Smem reads in phase 2 are SCALAR (stride 65 is
// not 16B-aligned per row; a float4 read there traps with misaligned address).
// ---------------------------------------------------------------------------
__global__ __launch_bounds__(256)
void vt_kernel(const float* __restrict__ qkv, float* __restrict__ vt){
    __shared__ float ts[64][65];
    int bh = blockIdx.y;               // 0..127
    int b = bh>>4, h = bh&15;
    int n0 = blockIdx.x*64;
    int tid = threadIdx.x;
    const float* src = qkv + (size_t)b*NN*QKVN + 2*INNER + h*DHEAD;
#pragma unroll
    for (int i = 0; i < 4; i++){
        int fid = tid + i*256;
        int r = fid>>4, c4 = (fid&15)*4;   // r = token row, c4 = d col
        float4 v = *(const float4*)&src[(size_t)(n0+r)*QKVN + c4];
        ts[c4+0][r] = v.x; ts[c4+1][r] = v.y; ts[c4+2][r] = v.z; ts[c4+3][r] = v.w;
    }
    __syncthreads();
    float* dst = vt + (size_t)bh*DHEAD*NN + n0;
#pragma unroll
    for (int i = 0; i < 4; i++){
        int fid = tid + i*256;
        int r = fid>>4, c4 = (fid&15)*4;   // r = d row, c4 = token col
        float4 o = make_float4(ts[r][c4+0], ts[r][c4+1], ts[r][c4+2], ts[r][c4+3]);
        *(float4*)&dst[(size_t)r*NN + c4] = o;
    }
}

// ---------------------------------------------------------------------------
// tf32 TC GEMM, templated tile. BK=32, 256 thr, warp tile 32 x (BN/WC).
// Inputs already tf32-rounded. cp.async double-buffered.
// bias==nullptr => output tf32-rounded (QKV path).
// ---------------------------------------------------------------------------
#define GA_STR 36

template<int BM, int BN, int WR, int WC>
__global__ __launch_bounds__(256, 2)
void gemm_tc(const float* __restrict__ A, const float* __restrict__ Bm,
             const float* __restrict__ bias, float* __restrict__ C,
             int M, int Nn, int K){
    constexpr int NFR   = (BN/WC)/8;     // 8-col frags per warp
    constexpr int AIT   = BM*8/256;      // 16B chunks per thread for A
    constexpr int BIT   = BN*8/256;      // 16B chunks per thread for B
    constexpr int BQ    = BN/4;          // float4 quads per B row
    constexpr int B_STR = BN + 8;        // (BN+8) % 32 == 8 -> conflict-free
    constexpr int ABUF  = BM*GA_STR;
    constexpr int BBUF  = 32*B_STR;
    extern __shared__ uint32_t smg[];
    uint32_t* As = smg;                  // 2 buffers
    uint32_t* Bs = smg + 2*ABUF;         // 2 buffers
    int m0 = blockIdx.y*BM, n0 = blockIdx.x*BN;
    int tid = threadIdx.x;
    int w = tid>>5, lane = tid&31;
    int g = lane>>2, t = lane&3;
    int wm = w / WC, wn = w % WC;
    uint32_t as_sh = (uint32_t)__cvta_generic_to_shared(As);
    uint32_t bs_sh = (uint32_t)__cvta_generic_to_shared(Bs);
    int a_sub = ((lane>>3)&1)*8 + (lane&7);
    int a_kh  = (lane>>4)*4;

    float acc[2][NFR][4] = {};

    auto issue = [&](int kt, int buf){
#pragma unroll
        for (int i = 0; i < AIT; i++){
            int fid = tid + i*256; int r = fid>>3, cq = fid&7;
            cpa16(as_sh + (uint32_t)(buf*ABUF + r*GA_STR + cq*4)*4,
                  &A[(size_t)(m0+r)*K + kt + cq*4]);
        }
#pragma unroll
        for (int i = 0; i < BIT; i++){
            int fid = tid + i*256; int r = fid/BQ, cq = fid%BQ;
            cpa16(bs_sh + (uint32_t)(buf*BBUF + r*B_STR + cq*4)*4,
                  &Bm[(size_t)(kt+r)*Nn + n0 + cq*4]);
        }
        cp_commit();
    };

    issue(0, 0);
    int nt = K/32;
    for (int it = 0; it < nt; it++){
        int buf = it & 1;
        cp_wait<0>();
        __syncthreads();
        if (it + 1 < nt) issue((it+1)*32, buf^1);
#pragma unroll
        for (int ks = 0; ks < 4; ks++){
            int k0 = ks*8;
            uint32_t af[2][4];
#pragma unroll
            for (int mf = 0; mf < 2; mf++){
                int row = wm*32 + mf*16 + a_sub;
                ldsm4(af[mf], as_sh + (uint32_t)(buf*ABUF + row*GA_STR + k0 + a_kh)*4);
            }
#pragma unroll
            for (int nf = 0; nf < NFR; nf++){
                int col = wn*(BN/WC) + nf*8 + g;
                uint32_t b0 = Bs[buf*BBUF + (k0+t)*B_STR + col];
                uint32_t b1 = Bs[buf*BBUF + (k0+4+t)*B_STR + col];
                mma_tf32(acc[0][nf], af[0][0],af[0][1],af[0][2],af[0][3], b0,b1);
                mma_tf32(acc[1][nf], af[1][0],af[1][1],af[1][2],af[1][3], b0,b1);
            }
        }
        __syncthreads();
    }
#pragma unroll
    for (int mf = 0; mf < 2; mf++){
#pragma unroll
        for (int nf = 0; nf < NFR; nf++){
            int row = m0 + wm*32 + mf*16 + g;
            int col = n0 + wn*(BN/WC) + nf*8 + t*2;
            if (bias){
                float bx = bias[col], by = bias[col+1];
                *(float2*)&C[(size_t)row*Nn + col] =
                    make_float2(acc[mf][nf][0]+bx, acc[mf][nf][1]+by);
                *(float2*)&C[(size_t)(row+8)*Nn + col] =
                    make_float2(acc[mf][nf][2]+bx, acc[mf][nf][3]+by);
            } else {   // QKV path: round to tf32 for downstream attention
                *(uint2*)&C[(size_t)row*Nn + col] =
                    make_uint2(f2tf(acc[mf][nf][0]), f2tf(acc[mf][nf][1]));
                *(uint2*)&C[(size_t)(row+8)*Nn + col] =
                    make_uint2(f2tf(acc[mf][nf][2]), f2tf(acc[mf][nf][3]));
            }
        }
    }
}

// ---------------------------------------------------------------------------
// Flash attention, tf32 TC. 256 thr, 128 q-rows/CTA (warp owns 16 rows).
// K from qkv, V from pre-transposed g_vt -> both B-frag paths use ldmatrix.
// cp.async double-buffered. Q frags in registers.
// ---------------------------------------------------------------------------
#define AT_STR 68
#define KBUF (64*AT_STR)
#define VBUF (64*AT_STR)
#define ATTN_SMEM_WORDS (128*AT_STR + 2*KBUF + 2*VBUF)
#define ATTN_SMEM_BYTES (ATTN_SMEM_WORDS*4)   // 104448

__global__ __launch_bounds__(256, 2)
void attn_tc(const float* __restrict__ qkv, const float* __restrict__ vt,
             float* __restrict__ out){
    extern __shared__ uint32_t sm[];
    uint32_t* Ps = sm;                    // 128 x AT_STR : Q staging, then P
    uint32_t* Ks = sm + 128*AT_STR;       // 2 buffers (keys x d)
    uint32_t* Vs = Ks + 2*KBUF;           // 2 buffers (d x keys, transposed)

    int qt = blockIdx.x, bh = blockIdx.y; // qt: 0..7 (128-row tiles)
    int b = bh>>4, h = bh&15;
    int tid = threadIdx.x, w = tid>>5, lane = tid&31;
    int g = lane>>2, t = lane&3;
    const float* base   = qkv + (size_t)b*NN*QKVN + h*DHEAD;
    const float* vtbase = vt + (size_t)bh*DHEAD*NN;

    uint32_t ps_sh = (uint32_t)__cvta_generic_to_shared(Ps);
    uint32_t ks_sh = (uint32_t)__cvta_generic_to_shared(Ks);
    uint32_t vs_sh = (uint32_t)__cvta_generic_to_shared(Vs);
    int a_row = w*16 + ((lane>>3)&1)*8 + (lane&7);
    uint32_t a_base = ps_sh + (uint32_t)(a_row*AT_STR + (lane>>4)*4)*4;
    // B-frag lane addressing (shared by K and Vt: 16 n-rows x 8 k per ldsm4)
    int kb_row = ((lane>>4)<<3) + (lane&7);
    uint32_t kb_off = (uint32_t)(kb_row*AT_STR + ((lane>>3)&1)*4)*4;

    // Q staging (values already tf32; *0.125 is exact) -> frags in regs
#pragma unroll
    for (int i = 0; i < 8; i++){
        int fid = tid + i*256;
        int r = fid>>4, cq = fid&15;
        float4 v = *(const float4*)&base[(size_t)(qt*128+r)*QKVN + cq*4];
        *(uint4*)&Ps[r*AT_STR + cq*4] = make_uint4(
            __float_as_uint(v.x*0.125f), __float_as_uint(v.y*0.125f),
            __float_as_uint(v.z*0.125f), __float_as_uint(v.w*0.125f));
    }
    __syncthreads();
    uint32_t qf[8][4];
#pragma unroll
    for (int ks = 0; ks < 8; ks++)
        ldsm4(qf[ks], a_base + ks*32);

    auto issue = [&](int kt, int buf){
#pragma unroll
        for (int i = 0; i < 4; i++){
            int fid = tid + i*256;
            int r = fid>>4, cq = fid&15;
            // K tile: rows = keys, cols = d
            cpa16(ks_sh + (uint32_t)(buf*KBUF + r*AT_STR + cq*4)*4,
                  &base[(size_t)(kt*64+r)*QKVN + INNER + cq*4]);
            // Vt tile: rows = d, cols = keys
            cpa16(vs_sh + (uint32_t)(buf*VBUF + r*AT_STR + cq*4)*4,
                  &vtbase[(size_t)r*NN + kt*64 + cq*4]);
        }
        cp_commit();
    };

    float o[8][4] = {};
    float mi0 = -INFINITY, mi1 = -INFINITY, li0 = 0.f, li1 = 0.f;

    issue(0, 0);
    for (int kt = 0; kt < 16; kt++){
        int buf = kt & 1;
        cp_wait<0>();
        __syncthreads();
        if (kt + 1 < 16) issue(kt+1, buf^1);

        // S = Q @ K^T
        float s[8][4] = {};
        uint32_t kbb = ks_sh + (uint32_t)(buf*KBUF)*4 + kb_off;
#pragma unroll
        for (int ks = 0; ks < 8; ks++){
            uint32_t* a = qf[ks];
#pragma unroll
            for (int nfp = 0; nfp < 4; nfp++){
                uint32_t kb[4];
                ldsm4(kb, kbb + (uint32_t)(nfp*16*AT_STR)*4 + ks*32);
                mma_tf32(s[2*nfp],   a[0],a[1],a[2],a[3], kb[0], kb[1]);
                mma_tf32(s[2*nfp+1], a[0],a[1],a[2],a[3], kb[2], kb[3]);
            }
        }

        // Online softmax (quad reduce over xor 1,2)
        float mx0 = -INFINITY, mx1 = -INFINITY;
#pragma unroll
        for (int nf = 0; nf < 8; nf++){
            mx0 = fmaxf(mx0, fmaxf(s[nf][0], s[nf][1]));
            mx1 = fmaxf(mx1, fmaxf(s[nf][2], s[nf][3]));
        }
        mx0 = fmaxf(mx0, __shfl_xor_sync(0xffffffffu, mx0, 1));
        mx0 = fmaxf(mx0, __shfl_xor_sync(0xffffffffu, mx0, 2));
        mx1 = fmaxf(mx1, __shfl_xor_sync(0xffffffffu, mx1, 1));
        mx1 = fmaxf(mx1, __shfl_xor_sync(0xffffffffu, mx1, 2));
        float mn0 = fmaxf(mi0, mx0), mn1 = fmaxf(mi1, mx1);
        float sc0 = __expf(mi0 - mn0), sc1 = __expf(mi1 - mn1);
        mi0 = mn0; mi1 = mn1;

        __syncwarp();      // prior PV reads of Ps done (warp-private rows)
        int prow = w*16 + g;
        float sum0 = 0.f, sum1 = 0.f;
#pragma unroll
        for (int nf = 0; nf < 8; nf++){
            float p0 = __expf(s[nf][0] - mn0), p1 = __expf(s[nf][1] - mn0);
            float p2 = __expf(s[nf][2] - mn1), p3 = __expf(s[nf][3] - mn1);
            sum0 += p0 + p1; sum1 += p2 + p3;
            int col = nf*8 + t*2;
            *(uint2*)&Ps[prow*AT_STR + col]     = make_uint2(f2tf(p0), f2tf(p1));
            *(uint2*)&Ps[(prow+8)*AT_STR + col] = make_uint2(f2tf(p2), f2tf(p3));
        }
        sum0 += __shfl_xor_sync(0xffffffffu, sum0, 1);
        sum0 += __shfl_xor_sync(0xffffffffu, sum0, 2);
        sum1 += __shfl_xor_sync(0xffffffffu, sum1, 1);
        sum1 += __shfl_xor_sync(0xffffffffu, sum1, 2);
        li0 = li0*sc0 + sum0;
        li1 = li1*sc1 + sum1;
#pragma unroll
        for (int nf = 0; nf < 8; nf++){
            o[nf][0] *= sc0; o[nf][1] *= sc0;
            o[nf][2] *= sc1; o[nf][3] *= sc1;
        }
        __syncwarp();

        // O += P @ V   (V B-frags via ldmatrix on transposed tile)
        uint32_t vbb = vs_sh + (uint32_t)(buf*VBUF)*4 + kb_off;
#pragma unroll
        for (int ks = 0; ks < 8; ks++){
            uint32_t pa[4];
            ldsm4(pa, a_base + ks*32);
#pragma unroll
            for (int dfp = 0; dfp < 4; dfp++){
                uint32_t vb[4];
                ldsm4(vb, vbb + (uint32_t)(dfp*16*AT_STR)*4 + ks*32);
                mma_tf32(o[2*dfp],   pa[0],pa[1],pa[2],pa[3], vb[0], vb[1]);
                mma_tf32(o[2*dfp+1], pa[0],pa[1],pa[2],pa[3], vb[2], vb[3]);
            }
        }
    }

    // Epilogue: tf32-round for the out-projection GEMM
    float inv0 = 1.f/li0, inv1 = 1.f/li1;
    int row = qt*128 + w*16 + g;
#pragma unroll
    for (int nf = 0; nf < 8; nf++){
        int col = h*DHEAD + nf*8 + t*2;
        *(uint2*)&out[((size_t)(b*NN+row))*INNER + col]   =
            make_uint2(f2tf(o[nf][0]*inv0), f2tf(o[nf][1]*inv0));
        *(uint2*)&out[((size_t)(b*NN+row+8))*INNER + col] =
            make_uint2(f2tf(o[nf][2]*inv1), f2tf(o[nf][3]*inv1));
    }
}

// ---------------------------------------------------------------------------
extern "C" void kernel_launch(void* const* d_in, const int* in_sizes, int n_in,
                              void* d_out, int out_size) {
    const float* x      = (const float*)d_in[0];
    const float* shift  = (const float*)d_in[1];
    const float* scale  = (const float*)d_in[2];
    const float* norm_w = (const float*)d_in[3];
    const float* norm_b = (const float*)d_in[4];
    const float* w_qkv  = (const float*)d_in[5];
    const float* w_out  = (const float*)d_in[6];
    const float* b_out  = (const float*)d_in[7];
    float* out = (float*)d_out;

    float *hp, *qkvp, *attnp, *wqp, *wop, *vtp;
    cudaGetSymbolAddress((void**)&hp,    g_h);
    cudaGetSymbolAddress((void**)&qkvp,  g_qkv);
    cudaGetSymbolAddress((void**)&attnp, g_attn);
    cudaGetSymbolAddress((void**)&wqp,   g_wqkv);
    cudaGetSymbolAddress((void**)&wop,   g_wout);
    cudaGetSymbolAddress((void**)&vtp,   g_vt);

    const int gsm_qkv = (2*128*GA_STR + 2*32*(128+8))*4;   // 71680
    const int gsm_out = (2*64*GA_STR  + 2*32*(64+8))*4;    // 36864
    cudaFuncSetAttribute((gemm_tc<128,128,4,2>),
                         cudaFuncAttributeMaxDynamicSharedMemorySize, gsm_qkv);
    cudaFuncSetAttribute((gemm_tc<64,64,2,4>),
                         cudaFuncAttributeMaxDynamicSharedMemorySize, gsm_out);
    cudaFuncSetAttribute(attn_tc,
                         cudaFuncAttributeMaxDynamicSharedMemorySize, ATTN_SMEM_BYTES);

    cvt_tf32_kernel<<<256, 256>>>(w_qkv, wqp, DIM*QKVN);
    cvt_tf32_kernel<<<128, 256>>>(w_out, wop, INNER*DIM);
    ln_mod_kernel<<<TOK/8, 256>>>(x, shift, scale, norm_w, norm_b);
    gemm_tc<128,128,4,2><<<dim3(QKVN/128, TOK/128), 256, gsm_qkv>>>(
        hp, wqp, nullptr, qkvp, TOK, QKVN, DIM);
    vt_kernel<<<dim3(16, BB*HEADS), 256>>>(qkvp, vtp);
    attn_tc<<<dim3(8, BB*HEADS), 256, ATTN_SMEM_BYTES>>>(qkvp, vtp, attnp);
    gemm_tc<64,64,2,4><<<dim3(DIM/64, TOK/64), 256, gsm_out>>>(
        attnp, wop, b_out, out, TOK, DIM, INNER);
}

// round 10
// speedup vs baseline: 1.0526x; 1.0526x over previous
#include <cuda_runtime.h>
#include <math.h>
#include <stdint.h>

#define BB 8
#define NN 1024
#define DIM 192
#define HEADS 16
#define DHEAD 64
#define INNER 1024
#define TOK (BB*NN)       // 8192
#define QKVN (3*INNER)    // 3072

// Scratch (allocation-free rule: __device__ globals)
__device__ float g_h[TOK*DIM];
__device__ float g_qkv[(size_t)TOK*QKVN];
__device__ float g_attn[(size_t)TOK*INNER];
__device__ float g_wqkv[DIM*QKVN];
__device__ float g_wout[INNER*DIM];

__device__ __forceinline__ uint32_t f2tf(float x){
    uint32_t u; asm("cvt.rna.tf32.f32 %0, %1;" : "=r"(u) : "f"(x)); return u;
}
__device__ __forceinline__ float ex2(float x){
    float y; asm("ex2.approx.f32 %0, %1;" : "=f"(y) : "f"(x)); return y;
}

// D += A@B, m16n8k8 tf32. c0=[g][2t], c1=[g][2t+1], c2=[g+8][2t], c3=[g+8][2t+1]
__device__ __forceinline__ void mma_tf32(float* c, uint32_t a0, uint32_t a1, uint32_t a2, uint32_t a3,
                                         uint32_t b0, uint32_t b1){
    asm volatile("mma.sync.aligned.m16n8k8.row.col.f32.tf32.tf32.f32 "
        "{%0,%1,%2,%3}, {%4,%5,%6,%7}, {%8,%9}, {%0,%1,%2,%3};"
        : "+f"(c[0]), "+f"(c[1]), "+f"(c[2]), "+f"(c[3])
        : "r"(a0), "r"(a1), "r"(a2), "r"(a3), "r"(b0), "r"(b1));
}

__device__ __forceinline__ void ldsm4(uint32_t* r, uint32_t saddr){
    asm volatile("ldmatrix.sync.aligned.m8n8.x4.shared.b16 {%0,%1,%2,%3}, [%4];"
        : "=r"(r[0]), "=r"(r[1]), "=r"(r[2]), "=r"(r[3]) : "r"(saddr));
}

__device__ __forceinline__ void cpa16(uint32_t dst, const void* src){
    asm volatile("cp.async.cg.shared.global [%0], [%1], 16;" :: "r"(dst), "l"(src));
}
__device__ __forceinline__ void cp_commit(){ asm volatile("cp.async.commit_group;"); }
template<int N> __device__ __forceinline__ void cp_wait(){
    asm volatile("cp.async.wait_group %0;" :: "n"(N));
}

// ---------------------------------------------------------------------------
// Elementwise fp32 -> tf32-rounded fp32 bits (for weights)
// ---------------------------------------------------------------------------
__global__ __launch_bounds__(256)
void cvt_tf32_kernel(const float* __restrict__ src, float* __restrict__ dst, int n){
    for (int i = blockIdx.x*256 + threadIdx.x; i < n; i += gridDim.x*256)
        dst[i] = __uint_as_float(f2tf(src[i]));
}

// ---------------------------------------------------------------------------
// LayerNorm + adaLN modulation: one warp per token; output tf32-rounded
// ---------------------------------------------------------------------------
__global__ __launch_bounds__(256)
void ln_mod_kernel(const float* __restrict__ x,
                   const float* __restrict__ shift,
                   const float* __restrict__ scale,
                   const float* __restrict__ w,
                   const float* __restrict__ bpar) {
    int warp = threadIdx.x >> 5;
    int lane = threadIdx.x & 31;
    int t = blockIdx.x * 8 + warp;
    const float* xr = x + (size_t)t * DIM;
    float v[6];
    float s = 0.f;
#pragma unroll
    for (int q = 0; q < 6; q++) { v[q] = xr[lane + q*32]; s += v[q]; }
#pragma unroll
    for (int o = 16; o; o >>= 1) s += __shfl_xor_sync(0xffffffffu, s, o);
    float mu = s * (1.f/DIM);
    float vs = 0.f;
#pragma unroll
    for (int q = 0; q < 6; q++) { float d = v[q]-mu; vs += d*d; }
#pragma unroll
    for (int o = 16; o; o >>= 1) vs += __shfl_xor_sync(0xffffffffu, vs, o);
    float rstd = rsqrtf(vs*(1.f/DIM) + 1e-5f);
    int bi = t >> 10;
#pragma unroll
    for (int q = 0; q < 6; q++) {
        int d = lane + q*32;
        float hn = (v[q]-mu)*rstd*w[d] + bpar[d];
        hn = hn * (1.f + scale[bi*DIM + d]) + shift[bi*DIM + d];
        g_h[(size_t)t*DIM + d] = __uint_as_float(f2tf(hn));
    }
}

// ---------------------------------------------------------------------------
// tf32 TC GEMM (mma.sync), templated tile. BK=32, 256 thr.
// Inputs already tf32-rounded. cp.async double-buffered.
// bias==nullptr => output tf32-rounded (QKV path).
// ---------------------------------------------------------------------------
#define GA_STR 36

template<int BM, int BN, int WR, int WC>
__global__ __launch_bounds__(256, 2)
void gemm_tc(const float* __restrict__ A, const float* __restrict__ Bm,
             const float* __restrict__ bias, float* __restrict__ C,
             int M, int Nn, int K){
    constexpr int NFR   = (BN/WC)/8;
    constexpr int AIT   = BM*8/256;
    constexpr int BIT   = BN*8/256;
    constexpr int BQ    = BN/4;
    constexpr int B_STR = BN + 8;        // (BN+8) % 32 == 8 -> conflict-free
    constexpr int ABUF  = BM*GA_STR;
    constexpr int BBUF  = 32*B_STR;
    extern __shared__ uint32_t smg[];
    uint32_t* As = smg;
    uint32_t* Bs = smg + 2*ABUF;
    int m0 = blockIdx.y*BM, n0 = blockIdx.x*BN;
    int tid = threadIdx.x;
    int w = tid>>5, lane = tid&31;
    int g = lane>>2, t = lane&3;
    int wm = w / WC, wn = w % WC;
    uint32_t as_sh = (uint32_t)__cvta_generic_to_shared(As);
    uint32_t bs_sh = (uint32_t)__cvta_generic_to_shared(Bs);
    int a_sub = ((lane>>3)&1)*8 + (lane&7);
    int a_kh  = (lane>>4)*4;

    float acc[2][NFR][4] = {};

    auto issue = [&](int kt, int buf){
#pragma unroll
        for (int i = 0; i < AIT; i++){
            int fid = tid + i*256; int r = fid>>3, cq = fid&7;
            cpa16(as_sh + (uint32_t)(buf*ABUF + r*GA_STR + cq*4)*4,
                  &A[(size_t)(m0+r)*K + kt + cq*4]);
        }
#pragma unroll
        for (int i = 0; i < BIT; i++){
            int fid = tid + i*256; int r = fid/BQ, cq = fid%BQ;
            cpa16(bs_sh + (uint32_t)(buf*BBUF + r*B_STR + cq*4)*4,
                  &Bm[(size_t)(kt+r)*Nn + n0 + cq*4]);
        }
        cp_commit();
    };

    issue(0, 0);
    int nt = K/32;
    for (int it = 0; it < nt; it++){
        int buf = it & 1;
        cp_wait<0>();
        __syncthreads();
        if (it + 1 < nt) issue((it+1)*32, buf^1);
#pragma unroll
        for (int ks = 0; ks < 4; ks++){
            int k0 = ks*8;
            uint32_t af[2][4];
#pragma unroll
            for (int mf = 0; mf < 2; mf++){
                int row = wm*32 + mf*16 + a_sub;
                ldsm4(af[mf], as_sh + (uint32_t)(buf*ABUF + row*GA_STR + k0 + a_kh)*4);
            }
#pragma unroll
            for (int nf = 0; nf < NFR; nf++){
                int col = wn*(BN/WC) + nf*8 + g;
                uint32_t b0 = Bs[buf*BBUF + (k0+t)*B_STR + col];
                uint32_t b1 = Bs[buf*BBUF + (k0+4+t)*B_STR + col];
                mma_tf32(acc[0][nf], af[0][0],af[0][1],af[0][2],af[0][3], b0,b1);
                mma_tf32(acc[1][nf], af[1][0],af[1][1],af[1][2],af[1][3], b0,b1);
            }
        }
        __syncthreads();
    }
#pragma unroll
    for (int mf = 0; mf < 2; mf++){
#pragma unroll
        for (int nf = 0; nf < NFR; nf++){
            int row = m0 + wm*32 + mf*16 + g;
            int col = n0 + wn*(BN/WC) + nf*8 + t*2;
            if (bias){
                float bx = bias[col], by = bias[col+1];
                *(float2*)&C[(size_t)row*Nn + col] =
                    make_float2(acc[mf][nf][0]+bx, acc[mf][nf][1]+by);
                *(float2*)&C[(size_t)(row+8)*Nn + col] =
                    make_float2(acc[mf][nf][2]+bx, acc[mf][nf][3]+by);
            } else {
                *(uint2*)&C[(size_t)row*Nn + col] =
                    make_uint2(f2tf(acc[mf][nf][0]), f2tf(acc[mf][nf][1]));
                *(uint2*)&C[(size_t)(row+8)*Nn + col] =
                    make_uint2(f2tf(acc[mf][nf][2]), f2tf(acc[mf][nf][3]));
            }
        }
    }
}

// ---------------------------------------------------------------------------
// Flash attention, tf32 mma.sync. 256 thr, 128 q-rows/CTA (warp owns 16 rows).
// Base-2 softmax: log2e folded into Q scale, ex2.approx for exponentials.
// ---------------------------------------------------------------------------
#define AT_STR 68
#define V_STR  72
#define KBUF (64*AT_STR)
#define VBUF (64*V_STR)
#define ATTN_SMEM_WORDS (128*AT_STR + 2*KBUF + 2*VBUF)
#define ATTN_SMEM_BYTES (ATTN_SMEM_WORDS*4)   // 106496
#define QSCALE 0.18033688f   // 0.125 * log2(e)

__global__ __launch_bounds__(256, 2)
void attn_tc(const float* __restrict__ qkv, float* __restrict__ out){
    extern __shared__ uint32_t sm[];
    uint32_t* Ps = sm;
    uint32_t* Ks = sm + 128*AT_STR;
    uint32_t* Vs = Ks + 2*KBUF;

    int qt = blockIdx.x, bh = blockIdx.y;
    int b = bh>>4, h = bh&15;
    int tid = threadIdx.x, w = tid>>5, lane = tid&31;
    int g = lane>>2, t = lane&3;
    const float* base = qkv + (size_t)b*NN*QKVN + h*DHEAD;

    uint32_t ps_sh = (uint32_t)__cvta_generic_to_shared(Ps);
    uint32_t ks_sh = (uint32_t)__cvta_generic_to_shared(Ks);
    uint32_t vs_sh = (uint32_t)__cvta_generic_to_shared(Vs);
    int a_row = w*16 + ((lane>>3)&1)*8 + (lane&7);
    uint32_t a_base = ps_sh + (uint32_t)(a_row*AT_STR + (lane>>4)*4)*4;
    int kb_row = ((lane>>4)<<3) + (lane&7);
    uint32_t kb_off = (uint32_t)(kb_row*AT_STR + ((lane>>3)&1)*4)*4;

    // Q staging with base-2 scale folded; re-round to tf32 after the scale
#pragma unroll
    for (int i = 0; i < 8; i++){
        int fid = tid + i*256;
        int r = fid>>4, cq = fid&15;
        float4 v = *(const float4*)&base[(size_t)(qt*128+r)*QKVN + cq*4];
        *(uint4*)&Ps[r*AT_STR + cq*4] = make_uint4(
            f2tf(v.x*QSCALE), f2tf(v.y*QSCALE), f2tf(v.z*QSCALE), f2tf(v.w*QSCALE));
    }
    __syncthreads();
    uint32_t qf[8][4];
#pragma unroll
    for (int ks = 0; ks < 8; ks++)
        ldsm4(qf[ks], a_base + ks*32);

    auto issue = [&](int kt, int buf){
#pragma unroll
        for (int i = 0; i < 4; i++){
            int fid = tid + i*256;
            int r = fid>>4, cq = fid&15;
            const float* kr = &base[(size_t)(kt*64+r)*QKVN + INNER + cq*4];
            cpa16(ks_sh + (uint32_t)(buf*KBUF + r*AT_STR + cq*4)*4, kr);
            cpa16(vs_sh + (uint32_t)(buf*VBUF + r*V_STR  + cq*4)*4, kr + INNER);
        }
        cp_commit();
    };

    float o[8][4] = {};
    float mi0 = -INFINITY, mi1 = -INFINITY, li0 = 0.f, li1 = 0.f;

    issue(0, 0);
    for (int kt = 0; kt < 16; kt++){
        int buf = kt & 1;
        cp_wait<0>();
        __syncthreads();
        if (kt + 1 < 16) issue(kt+1, buf^1);

        // S = Q @ K^T   (scores already in log2 domain)
        float s[8][4] = {};
        uint32_t kbb = ks_sh + (uint32_t)(buf*KBUF)*4 + kb_off;
#pragma unroll
        for (int ks = 0; ks < 8; ks++){
            uint32_t* a = qf[ks];
#pragma unroll
            for (int nfp = 0; nfp < 4; nfp++){
                uint32_t kb[4];
                ldsm4(kb, kbb + (uint32_t)(nfp*16*AT_STR)*4 + ks*32);
                mma_tf32(s[2*nfp],   a[0],a[1],a[2],a[3], kb[0], kb[1]);
                mma_tf32(s[2*nfp+1], a[0],a[1],a[2],a[3], kb[2], kb[3]);
            }
        }

        // Online softmax, base 2 (quad reduce over xor 1,2)
        float mx0 = -INFINITY, mx1 = -INFINITY;
#pragma unroll
        for (int nf = 0; nf < 8; nf++){
            mx0 = fmaxf(mx0, fmaxf(s[nf][0], s[nf][1]));
            mx1 = fmaxf(mx1, fmaxf(s[nf][2], s[nf][3]));
        }
        mx0 = fmaxf(mx0, __shfl_xor_sync(0xffffffffu, mx0, 1));
        mx0 = fmaxf(mx0, __shfl_xor_sync(0xffffffffu, mx0, 2));
        mx1 = fmaxf(mx1, __shfl_xor_sync(0xffffffffu, mx1, 1));
        mx1 = fmaxf(mx1, __shfl_xor_sync(0xffffffffu, mx1, 2));
        float mn0 = fmaxf(mi0, mx0), mn1 = fmaxf(mi1, mx1);
        float sc0 = ex2(mi0 - mn0), sc1 = ex2(mi1 - mn1);
        mi0 = mn0; mi1 = mn1;

        __syncwarp();      // prior PV reads of Ps done (warp-private rows)
        int prow = w*16 + g;
        float sum0 = 0.f, sum1 = 0.f;
#pragma unroll
        for (int nf = 0; nf < 8; nf++){
            float p0 = ex2(s[nf][0] - mn0), p1 = ex2(s[nf][1] - mn0);
            float p2 = ex2(s[nf][2] - mn1), p3 = ex2(s[nf][3] - mn1);
            sum0 += p0 + p1; sum1 += p2 + p3;
            int col = nf*8 + t*2;
            *(uint2*)&Ps[prow*AT_STR + col]     = make_uint2(f2tf(p0), f2tf(p1));
            *(uint2*)&Ps[(prow+8)*AT_STR + col] = make_uint2(f2tf(p2), f2tf(p3));
        }
        sum0 += __shfl_xor_sync(0xffffffffu, sum0, 1);
        sum0 += __shfl_xor_sync(0xffffffffu, sum0, 2);
        sum1 += __shfl_xor_sync(0xffffffffu, sum1, 1);
        sum1 += __shfl_xor_sync(0xffffffffu, sum1, 2);
        li0 = li0*sc0 + sum0;
        li1 = li1*sc1 + sum1;
#pragma unroll
        for (int nf = 0; nf < 8; nf++){
            o[nf][0] *= sc0; o[nf][1] *= sc0;
            o[nf][2] *= sc1; o[nf][3] *= sc1;
        }
        __syncwarp();

        // O += P @ V
#pragma unroll
        for (int ks = 0; ks < 8; ks++){
            int k0 = ks*8;
            uint32_t pa[4];
            ldsm4(pa, a_base + ks*32);
#pragma unroll
            for (int nf = 0; nf < 8; nf++){
                int d0 = nf*8 + g;
                uint32_t b0 = Vs[buf*VBUF + (k0+t)*V_STR + d0];
                uint32_t b1 = Vs[buf*VBUF + (k0+4+t)*V_STR + d0];
                mma_tf32(o[nf], pa[0],pa[1],pa[2],pa[3], b0, b1);
            }
        }
    }

    // Epilogue: tf32-round for the out-projection GEMM
    float inv0 = 1.f/li0, inv1 = 1.f/li1;
    int row = qt*128 + w*16 + g;
#pragma unroll
    for (int nf = 0; nf < 8; nf++){
        int col = h*DHEAD + nf*8 + t*2;
        *(uint2*)&out[((size_t)(b*NN+row))*INNER + col]   =
            make_uint2(f2tf(o[nf][0]*inv0), f2tf(o[nf][1]*inv0));
        *(uint2*)&out[((size_t)(b*NN+row+8))*INNER + col] =
            make_uint2(f2tf(o[nf][2]*inv1), f2tf(o[nf][3]*inv1));
    }
}

// ---------------------------------------------------------------------------
extern "C" void kernel_launch(void* const* d_in, const int* in_sizes, int n_in,
                              void* d_out, int out_size) {
    const float* x      = (const float*)d_in[0];
    const float* shift  = (const float*)d_in[1];
    const float* scale  = (const float*)d_in[2];
    const float* norm_w = (const float*)d_in[3];
    const float* norm_b = (const float*)d_in[4];
    const float* w_qkv  = (const float*)d_in[5];
    const float* w_out  = (const float*)d_in[6];
    const float* b_out  = (const float*)d_in[7];
    float* out = (float*)d_out;

    float *hp, *qkvp, *attnp, *wqp, *wop;
    cudaGetSymbolAddress((void**)&hp,    g_h);
    cudaGetSymbolAddress((void**)&qkvp,  g_qkv);
    cudaGetSymbolAddress((void**)&attnp, g_attn);
    cudaGetSymbolAddress((void**)&wqp,   g_wqkv);
    cudaGetSymbolAddress((void**)&wop,   g_wout);

    const int gsm_qkv = (2*128*GA_STR + 2*32*(128+8))*4;   // 71680
    const int gsm_out = (2*64*GA_STR  + 2*32*(64+8))*4;    // 36864
    cudaFuncSetAttribute((gemm_tc<128,128,4,2>),
                         cudaFuncAttributeMaxDynamicSharedMemorySize, gsm_qkv);
    cudaFuncSetAttribute((gemm_tc<64,64,2,4>),
                         cudaFuncAttributeMaxDynamicSharedMemorySize, gsm_out);
    cudaFuncSetAttribute(attn_tc,
                         cudaFuncAttributeMaxDynamicSharedMemorySize, ATTN_SMEM_BYTES);

    // Launch order chosen so attn_tc is the 4th replay launch (ncu capture slot).
    cvt_tf32_kernel<<<256, 256>>>(w_qkv, wqp, DIM*QKVN);
    ln_mod_kernel<<<TOK/8, 256>>>(x, shift, scale, norm_w, norm_b);
    gemm_tc<128,128,4,2><<<dim3(QKVN/128, TOK/128), 256, gsm_qkv>>>(
        hp, wqp, nullptr, qkvp, TOK, QKVN, DIM);
    attn_tc<<<dim3(8, BB*HEADS), 256, ATTN_SMEM_BYTES>>>(qkvp, attnp);
    cvt_tf32_kernel<<<128, 256>>>(w_out, wop, INNER*DIM);
    gemm_tc<64,64,2,4><<<dim3(DIM/64, TOK/64), 256, gsm_out>>>(
        attnp, wop, b_out, out, TOK, DIM, INNER);
}